// round 15
// baseline (speedup 1.0000x reference)
#include <cuda_runtime.h>

// ---------------------------------------------------------------------------
// TemporalFootAndBall detection post-process, GB300 (sm_103a)  -- R15
//
// R15 vs R14 (fused, 39.1us): two scheduling fixes, logic unchanged.
//  1. Select CTAs FIRST in bid order (0..127) -> resident from wave 1,
//     overlapping NMS the whole run instead of running after it.
//  2. __launch_bounds__(512, 3): cap regs at 42 (R14's 61-reg union dropped
//     occupancy to 2 CTAs/SM and stretched the NMS makespan).
// ---------------------------------------------------------------------------

#define B_DIM   64
#define P_H     68
#define P_W     120
#define P_HW    (P_H * P_W)
#define B_H     272
#define B_W     480
#define B_HW    (B_H * B_W)
#define MAXDET  100

#define NROWS      17                // rows per warp strip (ball & player)
#define CHUNKS_B   16                // ball row-chunks per batch (16*17=272)
#define CAP_B      (NROWS * B_W)     // 8160 (cap = pixels in chunk: safe)
#define BALL_CTAS  (B_DIM * CHUNKS_B)  // 1024
#define SEL_CTAS   (2 * B_DIM)         // 128 select CTAs (bids 0..127)
#define NMS0       SEL_CTAS            // first NMS bid
#define GRID_CTAS  (SEL_CTAS + BALL_CTAS + B_DIM)

#define NWARP   16
#define WCAP    64                   // per-warp deferred-keeper buffer
#define CAP     1024                 // select collect buffer
#define NT      512                  // threads per CTA (uniform)

// Static scratch (allocation-free).
__device__ unsigned long long g_cand_b[(size_t)BALL_CTAS * CAP_B];
__device__ unsigned long long g_cand_p[B_DIM * P_HW];
__device__ int g_cnt_b[BALL_CTAS];   // plain stores, rewritten every launch
__device__ int g_cnt_p[B_DIM];
__device__ int g_ready[2 * B_DIM];   // per-row producer counters (self-reset)

// Bit-exact replication of libdevice __nv_expf (XLA's f32 exp) for args in
// (-88, 0]. fma/exact-scale only -> fast-math-proof.
__device__ __forceinline__ float xla_expf(float a) {
    float j = fmaf(a, 0x1.715476p+0f, 0x1.8p+23f) - 0x1.8p+23f;  // rint
    float f = fmaf(j, -0x1.62e400p-1f, a);
    f = fmaf(j, -0x1.7f7d1cp-20f, f);
    const int i = (int)j;
    float r = 0x1.694000p-10f;
    r = fmaf(r, f, 0x1.125edcp-7f);
    r = fmaf(r, f, 0x1.555b5ap-5f);
    r = fmaf(r, f, 0x1.555450p-3f);
    r = fmaf(r, f, 0x1.fffff6p-2f);
    r = fmaf(r, f, 1.0f);
    r = fmaf(r, f, 1.0f);
    return r * __uint_as_float((unsigned)(127 + i) << 23);
}

// softmax([x0,x1])[1] as a function of d = x1-x0, bit-identical to
// m=max; e=exp(min-m); conf=e1/(1+e) with IEEE ops.
__device__ __forceinline__ float conf_from_d(float d) {
    const float e = xla_expf(0.0f - fabsf(d));
    const float e1 = (d >= 0.0f) ? 1.0f : e;
    return __fdiv_rn(e1, 1.0f + e);
}

// Range-adaptive monotone bin map for conf keys (conf in (0,1]):
//   key >= 0x3F000000 (conf >= 0.5): mantissa bins, 2^12 ulps wide
//   else: exponent bins (coarse; sparse population)
__device__ __forceinline__ unsigned key_bin(unsigned key) {
    return (key >= 0x3F000000u) ? (128u + ((key - 0x3F000000u) >> 12))
                                : (key >> 23);
}
__device__ __forceinline__ unsigned bin_lo(unsigned b) {
    return (b >= 128u) ? (0x3F000000u + ((b - 128u) << 12)) : (b << 23);
}
__device__ __forceinline__ int bin_shift(unsigned b) {
    return (b >= 128u) ? 0 : 11;   // sub-bin width shift for level-1
}

// Drain a warp's deferred-keeper buffer: compute exact conf keys in bulk
// (all lanes parallel) and write to the CTA's global segment.
__device__ __forceinline__ void warp_flush(unsigned long long* wb, int cnt,
                                           unsigned long long* seg,
                                           int* s_cnt, int lane) {
    if (cnt == 0) return;
    int base = 0;
    if (lane == 0) base = atomicAdd(s_cnt, cnt);
    base = __shfl_sync(0xFFFFFFFFu, base, 0);
    for (int i = lane; i < cnt; i += 32) {   // no collectives inside
        const unsigned long long e = wb[i];
        const float d = __uint_as_float((unsigned)(e >> 32));
        const unsigned key = __float_as_uint(conf_from_d(d));
        seg[base + i] = ((unsigned long long)key << 32) | (unsigned)e;
    }
}

// ---------------------------------------------------------------------------
// NMS strip worker: one warp owns a 30-output-column x NROWS strip. All
// NROWS+2 halo rows of d = x1-x0 are loaded into registers up-front (single
// latency wait), then the 3x3 NMS runs register-resident.
// ---------------------------------------------------------------------------
template <int H, int W>
__device__ __forceinline__ void nms_strip(const float* __restrict__ f0,
                                          int gx, int y0,
                                          unsigned long long* wb,
                                          unsigned long long* seg,
                                          int* s_cnt, int lane) {
    const float* f1 = f0 + H * W;
    const bool inx = (gx >= 0 && gx < W);
    const bool owner = inx && lane >= 1 && lane <= 30;
    const float NINF = __int_as_float(0xFF800000);

    // Batch-load all halo rows (independent loads -> full MLP).
    float d[NROWS + 2];
    #pragma unroll
    for (int i = 0; i < NROWS + 2; ++i) {
        const int y = y0 - 1 + i;
        d[i] = NINF;
        if (inx && y >= 0 && y < H) {
            const int o = y * W + gx;
            d[i] = f1[o] - f0[o];
        }
    }

    int wcnt = 0;
    int rowbase = y0 * W;
    #pragma unroll
    for (int r = 0; r < NROWS; ++r) {
        const float vm = fmaxf(fmaxf(d[r], d[r + 1]), d[r + 2]);
        const float vl = __shfl_up_sync(0xFFFFFFFFu, vm, 1);
        const float vr = __shfl_down_sync(0xFFFFFFFFu, vm, 1);
        const float p  = fmaxf(vm, fmaxf(vl, vr));  // pooled 3x3 max (incl c)

        const float c = d[r + 1];
        bool kept = owner && (c == p);
        // Near-tie guard (per-lane, no ballot): conf bits can collapse only
        // if (p-c) <= 2^-18 * e^{dm}; exponent test, 1-bit slack each way.
        if (owner && !kept) {
            const float dd = p - c;
            const float dmx = fmaxf(fabsf(c), fabsf(p));
            const int E = (int)((__float_as_uint(dd) >> 23) & 255u) - 127;
            if ((float)E < fmaf(dmx, 1.442695041f, -15.0f)) {
                if (__float_as_uint(conf_from_d(c)) ==
                    __float_as_uint(conf_from_d(p)))
                    kept = true;
            }
        }

        const unsigned bal = __ballot_sync(0xFFFFFFFFu, kept);
        if (wcnt + 32 > WCAP) {                  // warp-uniform flush check
            warp_flush(wb, wcnt, seg, s_cnt, lane);
            wcnt = 0;
        }
        if (kept)
            wb[wcnt + __popc(bal & ((1u << lane) - 1u))] =
                ((unsigned long long)__float_as_uint(c) << 32) |
                (unsigned)(rowbase + gx);
        wcnt += __popc(bal);
        rowbase += W;
    }
    warp_flush(wb, wcnt, seg, s_cnt, lane);
}

// ---------------------------------------------------------------------------
// Block suffix scan over NT partials (16 warps) using shuffles (2 barriers).
// ---------------------------------------------------------------------------
__device__ __forceinline__ void block_suffix16(unsigned part, unsigned* wsum,
                                               int wid, int lane,
                                               unsigned& sfx,
                                               unsigned& total) {
    unsigned s = part;
    #pragma unroll
    for (int d = 1; d < 32; d <<= 1) {
        const unsigned v = __shfl_down_sync(0xFFFFFFFFu, s, d);
        if (lane + d < 32) s += v;
    }
    if (lane == 0) wsum[wid] = s;
    __syncthreads();
    unsigned t = (lane < NWARP) ? wsum[lane] : 0u;  // 16 warp totals
    #pragma unroll
    for (int d = 1; d < 32; d <<= 1) {
        const unsigned v = __shfl_down_sync(0xFFFFFFFFu, t, d);
        if (lane + d < 32) t += v;
    }
    total = __shfl_sync(0xFFFFFFFFu, t, 0);
    const unsigned carry = __shfl_sync(0xFFFFFFFFu, t, wid + 1);  // lane16=0
    sfx = s + carry;
    __syncthreads();                   // wsum reusable afterwards
}

// ---------------------------------------------------------------------------
// Fused kernel. bids [0,128): per-row select consumers (spin on g_ready);
// [128, 128+1024): ball NMS; remainder: player NMS.
// ---------------------------------------------------------------------------
__global__ __launch_bounds__(NT, 3) void fused_kernel(
    const float* __restrict__ pfm, const float* __restrict__ bfm,
    const float* __restrict__ pbb, float* __restrict__ out) {
    __shared__ union {
        struct { unsigned long long wbuf[NWARP][WCAP]; } n;
        struct {
            unsigned hist[4096];
            unsigned wsum[NWARP];
            unsigned long long buf[CAP];
            int cnts[CHUNKS_B];
        } s;
    } sm;
    __shared__ unsigned sh_b0, sh_above0, sh_set0, sh_thresh, sh_cnt, sh_done;
    __shared__ int s_cnt;

    const int tid = threadIdx.x, wid = tid >> 5, lane = tid & 31;

    if (blockIdx.x >= SEL_CTAS) {
        // ======================= NMS producer =======================
        const int nbid = blockIdx.x - NMS0;
        if (tid == 0) s_cnt = 0;
        __syncthreads();
        int row;
        if (nbid < BALL_CTAS) {
            const int b = nbid >> 4, chunk = nbid & 15;
            nms_strip<B_H, B_W>(bfm + (size_t)b * 2 * B_HW,
                                wid * 30 + lane - 1, chunk * NROWS,
                                sm.n.wbuf[wid],
                                g_cand_b + (size_t)nbid * CAP_B,
                                &s_cnt, lane);
            row = b;
        } else {
            const int b = nbid - BALL_CTAS;
            const int wcol = wid & 3, rc = wid >> 2;  // 4 cols x 4 chunks
            nms_strip<P_H, P_W>(pfm + (size_t)b * 2 * P_HW,
                                wcol * 30 + lane - 1, rc * NROWS,
                                sm.n.wbuf[wid],
                                g_cand_p + (size_t)b * P_HW,
                                &s_cnt, lane);
            row = B_DIM + b;
        }
        __syncthreads();
        if (tid == 0) {
            if (nbid < BALL_CTAS) g_cnt_b[nbid] = s_cnt;
            else                  g_cnt_p[nbid - BALL_CTAS] = s_cnt;
            __threadfence();                     // release candidates+count
            atomicAdd(&g_ready[row], 1);
        }
        return;
    }

    // ======================= select consumer =======================
    const int srow = blockIdx.x;                 // 0..127
    const bool is_player = (srow >= B_DIM);
    const int b = is_player ? srow - B_DIM : srow;
    const int expected = is_player ? 1 : CHUNKS_B;
    if (tid == 0) {
        while (atomicAdd(&g_ready[srow], 0) < expected) __nanosleep(200);
        __threadfence();                         // acquire
        g_ready[srow] = 0;                       // reset for next replay
    }
    __syncthreads();

    const int nseg = is_player ? 1 : CHUNKS_B;
    const int myseg = wid & (nseg - 1);          // warp's segment
    const int sub = wid / nseg;                  // warp index within segment
    const int sstride = (NWARP / nseg) * 32;     // lanes per segment per iter

    if (tid < nseg)
        sm.s.cnts[tid] = is_player ? g_cnt_p[b] : g_cnt_b[b * CHUNKS_B + tid];
    if (tid == 0) { sh_cnt = 0; sh_done = 0; sh_thresh = 0; }
    for (int i = tid; i < 4096; i += NT) sm.s.hist[i] = 0;
    __syncthreads();

    const unsigned long long* const segp =
        is_player ? (g_cand_p + (size_t)b * P_HW)
                  : (g_cand_b + (size_t)(b * CHUNKS_B + myseg) * CAP_B);
    const int mycnt = sm.s.cnts[myseg];          // warp-uniform
    const int mynit = (mycnt + sstride - 1) / sstride;
    const int lbase = sub * 32 + lane;

    // ---- Level 0 histogram (range-adaptive bins) ----
    for (int it = 0; it < mynit; it += 4) {
        unsigned bins[4];
        bool on[4];
        #pragma unroll
        for (int k = 0; k < 4; ++k) {
            const int i = (it + k) * sstride + lbase;
            on[k] = (i < mycnt);
            bins[k] = on[k] ? key_bin((unsigned)(segp[i] >> 32)) : 0u;
        }
        #pragma unroll
        for (int k = 0; k < 4; ++k)
            if (on[k]) atomicAdd(&sm.s.hist[bins[k]], 1u);
    }
    __syncthreads();

    {
        unsigned hh[8], part = 0;
        #pragma unroll
        for (int j = 0; j < 8; ++j) { hh[j] = sm.s.hist[8 * tid + j]; part += hh[j]; }
        unsigned sfx, total;
        block_suffix16(part, sm.s.wsum, wid, lane, sfx, total);
        const unsigned sfxn = sfx - part;
        if (total < (unsigned)MAXDET) {
            if (tid == 0) sh_done = 1;           // collect-all path
        } else if (sfx >= (unsigned)MAXDET && sfxn < (unsigned)MAXDET) {
            unsigned acc = sfxn;
            for (int k = 7; k >= 0; --k) {
                if (acc + hh[k] >= (unsigned)MAXDET) {
                    sh_b0 = (unsigned)(8 * tid + k);
                    sh_above0 = acc;
                    sh_set0 = acc + hh[k];
                    break;
                }
                acc += hh[k];
            }
        }
    }
    __syncthreads();

    unsigned thresh = 0;
    if (!sh_done) {
        if (sh_set0 <= 168u) {                   // common: fine bins
            thresh = bin_lo(sh_b0);
        } else {
            // ---- Level 1 within boundary bin (generic sub-bins) ----
            const unsigned b0 = sh_b0;
            const unsigned lo = bin_lo(b0);
            const int sh = bin_shift(b0);        // 0 (exact) or 11
            const unsigned target = (unsigned)MAXDET - sh_above0;
            for (int i = tid; i < 4096; i += NT) sm.s.hist[i] = 0;
            __syncthreads();
            for (int it = 0; it < mynit; it += 4) {
                unsigned sc[4];
                bool on[4];
                #pragma unroll
                for (int k = 0; k < 4; ++k) {
                    const int i = (it + k) * sstride + lbase;
                    const bool v = (i < mycnt);
                    sc[k] = v ? (unsigned)(segp[i] >> 32) : 0u;
                    on[k] = v && (key_bin(sc[k]) == b0);
                }
                #pragma unroll
                for (int k = 0; k < 4; ++k)
                    if (on[k])
                        atomicAdd(&sm.s.hist[((sc[k] - lo) >> sh) & 0xFFFu], 1u);
            }
            __syncthreads();
            unsigned hh[8], part = 0;
            #pragma unroll
            for (int j = 0; j < 8; ++j) { hh[j] = sm.s.hist[8 * tid + j]; part += hh[j]; }
            unsigned sfx, total;
            block_suffix16(part, sm.s.wsum, wid, lane, sfx, total);
            const unsigned sfxn = sfx - part;
            if (sfx >= target && sfxn < target) {  // total >= target holds
                unsigned acc = sfxn;
                for (int k = 7; k >= 0; --k) {
                    if (acc + hh[k] >= target) {
                        sh_thresh = lo + ((unsigned)(8 * tid + k) << sh);
                        break;
                    }
                    acc += hh[k];
                }
            }
            __syncthreads();
            thresh = sh_thresh;
        }
    }

    // ---- Collect candidates >= thresh ----
    // key = (conf_bits<<32) | ~idx : larger == (higher conf, lower idx)
    // == lax.top_k order.
    for (int it = 0; it < mynit; it += 4) {
        unsigned long long cv[4];
        bool keep[4];
        #pragma unroll
        for (int k = 0; k < 4; ++k) {
            const int i = (it + k) * sstride + lbase;
            const bool v = (i < mycnt);
            cv[k] = v ? segp[i] : 0ull;
            keep[k] = v && ((unsigned)(cv[k] >> 32) >= thresh);
        }
        #pragma unroll
        for (int k = 0; k < 4; ++k)
            if (keep[k]) {
                const unsigned pos = atomicAdd(&sh_cnt, 1u);
                if (pos < (unsigned)CAP)
                    sm.s.buf[pos] = (cv[k] & 0xFFFFFFFF00000000ull) |
                                    (unsigned)(~(unsigned)cv[k]);
            }
    }
    __syncthreads();
    const int m = (int)min(sh_cnt, (unsigned)CAP);

    // ---- Rank-based emission (keys distinct -> ranks a permutation) ----
    float* const orow = out + (size_t)b * (2 * MAXDET * 5) +
                        (is_player ? 0 : MAXDET * 5);
    for (int i = tid; i < m; i += NT) {
        const unsigned long long k = sm.s.buf[i];
        int rank = 0;
        for (int j = 0; j < m; ++j) rank += (sm.s.buf[j] > k);
        if (rank < MAXDET) {
            const unsigned idx = ~(unsigned)k;
            const float conf = __uint_as_float((unsigned)(k >> 32));
            float o0, o1, o2, o3;
            if (is_player) {
                const int x = (int)idx % P_W;
                const int y = (int)idx / P_W;
                const float xc = (float)x * 16.0f + 7.5f;
                const float yc = (float)y * 16.0f + 7.5f;
                const float* bp = pbb + (size_t)b * 4 * P_HW + idx;
                const float t0 = bp[0 * P_HW] * 1920.0f;
                const float t1 = bp[1 * P_HW] * 1088.0f;
                const float t2 = bp[2 * P_HW] * 1920.0f;
                const float t3 = bp[3 * P_HW] * 1088.0f;
                const float bx = xc + t0, by = yc + t1;
                o0 = bx - 0.5f * t2;
                o1 = by - 0.5f * t3;
                o2 = bx + 0.5f * t2;
                o3 = by + 0.5f * t3;
            } else {
                const int x = (int)idx % B_W;
                const int y = (int)idx / B_W;
                const float xc = (float)x * 4.0f + 1.5f;
                const float yc = (float)y * 4.0f + 1.5f;
                o0 = xc - 10.0f;
                o1 = yc - 10.0f;
                o2 = xc + 10.0f;
                o3 = yc + 10.0f;
            }
            float* op = orow + rank * 5;
            op[0] = o0; op[1] = o1; op[2] = o2; op[3] = o3; op[4] = conf;
        }
    }
    if (m < MAXDET) {  // pathological; never hit with this data
        for (int r = m + tid; r < MAXDET; r += NT) {
            float* op = orow + r * 5;
            op[0] = op[1] = op[2] = op[3] = op[4] = 0.0f;
        }
    }
}

// ---------------------------------------------------------------------------

extern "C" void kernel_launch(void* const* d_in, const int* in_sizes, int n_in,
                              void* d_out, int out_size) {
    const float* pfm = nullptr;
    const float* pbb = nullptr;
    const float* bfm = nullptr;
    for (int i = 0; i < n_in; ++i) {
        if (in_sizes[i] == B_DIM * 2 * P_HW)      pfm = (const float*)d_in[i];
        else if (in_sizes[i] == B_DIM * 4 * P_HW) pbb = (const float*)d_in[i];
        else if (in_sizes[i] == B_DIM * 2 * B_HW) bfm = (const float*)d_in[i];
    }
    float* out = (float*)d_out;

    fused_kernel<<<GRID_CTAS, NT>>>(pfm, bfm, pbb, out);
}

// round 16
// speedup vs baseline: 1.0394x; 1.0394x over previous
#include <cuda_runtime.h>

// ---------------------------------------------------------------------------
// TemporalFootAndBall detection post-process, GB300 (sm_103a)  -- R16
//
// R16: fusion WITHOUT waiter CTAs. R14/R15 showed dedicated consumer CTAs
// waste residency (spinners held ~29% of slots doing nothing -> NMS
// stretched). Now the grid is NMS CTAs only (1088); each producer signals
// g_ready[row]; the LAST arriver for a row runs that row's select in place
// (its NMS smem is dead by then -> union reuse). Zero idle CTAs, full
// overlap, one launch. Select body identical to R13/R15 (range-adaptive
// bins, suffix scan, collect, rank-emit). g_ready self-resets -> replay-safe.
// ---------------------------------------------------------------------------

#define B_DIM   64
#define P_H     68
#define P_W     120
#define P_HW    (P_H * P_W)
#define B_H     272
#define B_W     480
#define B_HW    (B_H * B_W)
#define MAXDET  100

#define NROWS      17                // rows per warp strip (ball & player)
#define CHUNKS_B   16                // ball row-chunks per batch (16*17=272)
#define CAP_B      (NROWS * B_W)     // 8160 (cap = pixels in chunk: safe)
#define BALL_CTAS  (B_DIM * CHUNKS_B)  // 1024
#define GRID_CTAS  (BALL_CTAS + B_DIM) // + 64 player CTAs = 1088

#define NWARP   16
#define WCAP    64                   // per-warp deferred-keeper buffer
#define CAP     1024                 // select collect buffer
#define NT      512                  // threads per CTA

// Static scratch (allocation-free).
__device__ unsigned long long g_cand_b[(size_t)BALL_CTAS * CAP_B];
__device__ unsigned long long g_cand_p[B_DIM * P_HW];
__device__ int g_cnt_b[BALL_CTAS];   // plain stores, rewritten every launch
__device__ int g_cnt_p[B_DIM];
__device__ int g_ready[2 * B_DIM];   // per-row arrival counters (self-reset)

// Bit-exact replication of libdevice __nv_expf (XLA's f32 exp) for args in
// (-88, 0]. fma/exact-scale only -> fast-math-proof.
__device__ __forceinline__ float xla_expf(float a) {
    float j = fmaf(a, 0x1.715476p+0f, 0x1.8p+23f) - 0x1.8p+23f;  // rint
    float f = fmaf(j, -0x1.62e400p-1f, a);
    f = fmaf(j, -0x1.7f7d1cp-20f, f);
    const int i = (int)j;
    float r = 0x1.694000p-10f;
    r = fmaf(r, f, 0x1.125edcp-7f);
    r = fmaf(r, f, 0x1.555b5ap-5f);
    r = fmaf(r, f, 0x1.555450p-3f);
    r = fmaf(r, f, 0x1.fffff6p-2f);
    r = fmaf(r, f, 1.0f);
    r = fmaf(r, f, 1.0f);
    return r * __uint_as_float((unsigned)(127 + i) << 23);
}

// softmax([x0,x1])[1] as a function of d = x1-x0, bit-identical to
// m=max; e=exp(min-m); conf=e1/(1+e) with IEEE ops.
__device__ __forceinline__ float conf_from_d(float d) {
    const float e = xla_expf(0.0f - fabsf(d));
    const float e1 = (d >= 0.0f) ? 1.0f : e;
    return __fdiv_rn(e1, 1.0f + e);
}

// Range-adaptive monotone bin map for conf keys (conf in (0,1]):
//   key >= 0x3F000000 (conf >= 0.5): mantissa bins, 2^12 ulps wide
//   else: exponent bins (coarse; sparse population)
__device__ __forceinline__ unsigned key_bin(unsigned key) {
    return (key >= 0x3F000000u) ? (128u + ((key - 0x3F000000u) >> 12))
                                : (key >> 23);
}
__device__ __forceinline__ unsigned bin_lo(unsigned b) {
    return (b >= 128u) ? (0x3F000000u + ((b - 128u) << 12)) : (b << 23);
}
__device__ __forceinline__ int bin_shift(unsigned b) {
    return (b >= 128u) ? 0 : 11;   // sub-bin width shift for level-1
}

// Drain a warp's deferred-keeper buffer: compute exact conf keys in bulk
// (all lanes parallel) and write to the CTA's global segment.
__device__ __forceinline__ void warp_flush(unsigned long long* wb, int cnt,
                                           unsigned long long* seg,
                                           int* s_cnt, int lane) {
    if (cnt == 0) return;
    int base = 0;
    if (lane == 0) base = atomicAdd(s_cnt, cnt);
    base = __shfl_sync(0xFFFFFFFFu, base, 0);
    for (int i = lane; i < cnt; i += 32) {   // no collectives inside
        const unsigned long long e = wb[i];
        const float d = __uint_as_float((unsigned)(e >> 32));
        const unsigned key = __float_as_uint(conf_from_d(d));
        seg[base + i] = ((unsigned long long)key << 32) | (unsigned)e;
    }
}

// ---------------------------------------------------------------------------
// NMS strip worker: one warp owns a 30-output-column x NROWS strip. All
// NROWS+2 halo rows of d = x1-x0 are loaded into registers up-front (single
// latency wait), then the 3x3 NMS runs register-resident.
// ---------------------------------------------------------------------------
template <int H, int W>
__device__ __forceinline__ void nms_strip(const float* __restrict__ f0,
                                          int gx, int y0,
                                          unsigned long long* wb,
                                          unsigned long long* seg,
                                          int* s_cnt, int lane) {
    const float* f1 = f0 + H * W;
    const bool inx = (gx >= 0 && gx < W);
    const bool owner = inx && lane >= 1 && lane <= 30;
    const float NINF = __int_as_float(0xFF800000);

    // Batch-load all halo rows (independent loads -> full MLP).
    float d[NROWS + 2];
    #pragma unroll
    for (int i = 0; i < NROWS + 2; ++i) {
        const int y = y0 - 1 + i;
        d[i] = NINF;
        if (inx && y >= 0 && y < H) {
            const int o = y * W + gx;
            d[i] = f1[o] - f0[o];
        }
    }

    int wcnt = 0;
    int rowbase = y0 * W;
    #pragma unroll
    for (int r = 0; r < NROWS; ++r) {
        const float vm = fmaxf(fmaxf(d[r], d[r + 1]), d[r + 2]);
        const float vl = __shfl_up_sync(0xFFFFFFFFu, vm, 1);
        const float vr = __shfl_down_sync(0xFFFFFFFFu, vm, 1);
        const float p  = fmaxf(vm, fmaxf(vl, vr));  // pooled 3x3 max (incl c)

        const float c = d[r + 1];
        bool kept = owner && (c == p);
        // Near-tie guard (per-lane, no ballot): conf bits can collapse only
        // if (p-c) <= 2^-18 * e^{dm}; exponent test, 1-bit slack each way.
        if (owner && !kept) {
            const float dd = p - c;
            const float dmx = fmaxf(fabsf(c), fabsf(p));
            const int E = (int)((__float_as_uint(dd) >> 23) & 255u) - 127;
            if ((float)E < fmaf(dmx, 1.442695041f, -15.0f)) {
                if (__float_as_uint(conf_from_d(c)) ==
                    __float_as_uint(conf_from_d(p)))
                    kept = true;
            }
        }

        const unsigned bal = __ballot_sync(0xFFFFFFFFu, kept);
        if (wcnt + 32 > WCAP) {                  // warp-uniform flush check
            warp_flush(wb, wcnt, seg, s_cnt, lane);
            wcnt = 0;
        }
        if (kept)
            wb[wcnt + __popc(bal & ((1u << lane) - 1u))] =
                ((unsigned long long)__float_as_uint(c) << 32) |
                (unsigned)(rowbase + gx);
        wcnt += __popc(bal);
        rowbase += W;
    }
    warp_flush(wb, wcnt, seg, s_cnt, lane);
}

// ---------------------------------------------------------------------------
// Block suffix scan over NT partials (16 warps) using shuffles (2 barriers).
// ---------------------------------------------------------------------------
__device__ __forceinline__ void block_suffix16(unsigned part, unsigned* wsum,
                                               int wid, int lane,
                                               unsigned& sfx,
                                               unsigned& total) {
    unsigned s = part;
    #pragma unroll
    for (int d = 1; d < 32; d <<= 1) {
        const unsigned v = __shfl_down_sync(0xFFFFFFFFu, s, d);
        if (lane + d < 32) s += v;
    }
    if (lane == 0) wsum[wid] = s;
    __syncthreads();
    unsigned t = (lane < NWARP) ? wsum[lane] : 0u;  // 16 warp totals
    #pragma unroll
    for (int d = 1; d < 32; d <<= 1) {
        const unsigned v = __shfl_down_sync(0xFFFFFFFFu, t, d);
        if (lane + d < 32) t += v;
    }
    total = __shfl_sync(0xFFFFFFFFu, t, 0);
    const unsigned carry = __shfl_sync(0xFFFFFFFFu, t, wid + 1);  // lane16=0
    sfx = s + carry;
    __syncthreads();                   // wsum reusable afterwards
}

// ---------------------------------------------------------------------------
// Fused kernel, last-arriver select. bids [0,1024): ball NMS chunks;
// [1024,1088): player NMS. After signaling, the 16th (ball) / 1st (player)
// arriver for a row runs that row's select in place.
// ---------------------------------------------------------------------------
__global__ __launch_bounds__(NT, 3) void fused_kernel(
    const float* __restrict__ pfm, const float* __restrict__ bfm,
    const float* __restrict__ pbb, float* __restrict__ out) {
    __shared__ union {
        struct { unsigned long long wbuf[NWARP][WCAP]; } n;
        struct {
            unsigned hist[4096];
            unsigned wsum[NWARP];
            unsigned long long buf[CAP];
            int cnts[CHUNKS_B];
        } s;
    } sm;
    __shared__ unsigned sh_b0, sh_above0, sh_set0, sh_thresh, sh_cnt, sh_done;
    __shared__ int s_cnt, sh_last;

    const int tid = threadIdx.x, wid = tid >> 5, lane = tid & 31;

    // ======================= NMS producer =======================
    if (tid == 0) s_cnt = 0;
    __syncthreads();
    int row;
    if (blockIdx.x < BALL_CTAS) {
        const int b = blockIdx.x >> 4, chunk = blockIdx.x & 15;
        nms_strip<B_H, B_W>(bfm + (size_t)b * 2 * B_HW,
                            wid * 30 + lane - 1, chunk * NROWS,
                            sm.n.wbuf[wid],
                            g_cand_b + (size_t)blockIdx.x * CAP_B,
                            &s_cnt, lane);
        row = b;
    } else {
        const int b = blockIdx.x - BALL_CTAS;
        const int wcol = wid & 3, rc = wid >> 2;  // 4 cols x 4 chunks
        nms_strip<P_H, P_W>(pfm + (size_t)b * 2 * P_HW,
                            wcol * 30 + lane - 1, rc * NROWS,
                            sm.n.wbuf[wid],
                            g_cand_p + (size_t)b * P_HW,
                            &s_cnt, lane);
        row = B_DIM + b;
    }
    __syncthreads();
    const int expected = (blockIdx.x < BALL_CTAS) ? CHUNKS_B : 1;
    if (tid == 0) {
        if (blockIdx.x < BALL_CTAS) g_cnt_b[blockIdx.x] = s_cnt;
        else                        g_cnt_p[blockIdx.x - BALL_CTAS] = s_cnt;
        __threadfence();                         // release candidates+count
        const int old = atomicAdd(&g_ready[row], 1);
        sh_last = (old == expected - 1);
        if (sh_last) {
            g_ready[row] = 0;                    // reset for next replay
            __threadfence();                     // order loads after acquire
        }
    }
    __syncthreads();
    if (!sh_last) return;

    // ================ select (last arriver, in place) ================
    const int srow = row;
    const bool is_player = (srow >= B_DIM);
    const int b = is_player ? srow - B_DIM : srow;

    const int nseg = is_player ? 1 : CHUNKS_B;
    const int myseg = wid & (nseg - 1);          // warp's segment
    const int sub = wid / nseg;                  // warp index within segment
    const int sstride = (NWARP / nseg) * 32;     // lanes per segment per iter

    if (tid < nseg)
        sm.s.cnts[tid] = is_player ? g_cnt_p[b] : g_cnt_b[b * CHUNKS_B + tid];
    if (tid == 0) { sh_cnt = 0; sh_done = 0; sh_thresh = 0; }
    for (int i = tid; i < 4096; i += NT) sm.s.hist[i] = 0;
    __syncthreads();

    const unsigned long long* const segp =
        is_player ? (g_cand_p + (size_t)b * P_HW)
                  : (g_cand_b + (size_t)(b * CHUNKS_B + myseg) * CAP_B);
    const int mycnt = sm.s.cnts[myseg];          // warp-uniform
    const int mynit = (mycnt + sstride - 1) / sstride;
    const int lbase = sub * 32 + lane;

    // ---- Level 0 histogram (range-adaptive bins) ----
    for (int it = 0; it < mynit; it += 4) {
        unsigned bins[4];
        bool on[4];
        #pragma unroll
        for (int k = 0; k < 4; ++k) {
            const int i = (it + k) * sstride + lbase;
            on[k] = (i < mycnt);
            bins[k] = on[k] ? key_bin((unsigned)(segp[i] >> 32)) : 0u;
        }
        #pragma unroll
        for (int k = 0; k < 4; ++k)
            if (on[k]) atomicAdd(&sm.s.hist[bins[k]], 1u);
    }
    __syncthreads();

    {
        unsigned hh[8], part = 0;
        #pragma unroll
        for (int j = 0; j < 8; ++j) { hh[j] = sm.s.hist[8 * tid + j]; part += hh[j]; }
        unsigned sfx, total;
        block_suffix16(part, sm.s.wsum, wid, lane, sfx, total);
        const unsigned sfxn = sfx - part;
        if (total < (unsigned)MAXDET) {
            if (tid == 0) sh_done = 1;           // collect-all path
        } else if (sfx >= (unsigned)MAXDET && sfxn < (unsigned)MAXDET) {
            unsigned acc = sfxn;
            for (int k = 7; k >= 0; --k) {
                if (acc + hh[k] >= (unsigned)MAXDET) {
                    sh_b0 = (unsigned)(8 * tid + k);
                    sh_above0 = acc;
                    sh_set0 = acc + hh[k];
                    break;
                }
                acc += hh[k];
            }
        }
    }
    __syncthreads();

    unsigned thresh = 0;
    if (!sh_done) {
        if (sh_set0 <= 168u) {                   // common: fine bins
            thresh = bin_lo(sh_b0);
        } else {
            // ---- Level 1 within boundary bin (generic sub-bins) ----
            const unsigned b0 = sh_b0;
            const unsigned lo = bin_lo(b0);
            const int sh = bin_shift(b0);        // 0 (exact) or 11
            const unsigned target = (unsigned)MAXDET - sh_above0;
            for (int i = tid; i < 4096; i += NT) sm.s.hist[i] = 0;
            __syncthreads();
            for (int it = 0; it < mynit; it += 4) {
                unsigned sc[4];
                bool on[4];
                #pragma unroll
                for (int k = 0; k < 4; ++k) {
                    const int i = (it + k) * sstride + lbase;
                    const bool v = (i < mycnt);
                    sc[k] = v ? (unsigned)(segp[i] >> 32) : 0u;
                    on[k] = v && (key_bin(sc[k]) == b0);
                }
                #pragma unroll
                for (int k = 0; k < 4; ++k)
                    if (on[k])
                        atomicAdd(&sm.s.hist[((sc[k] - lo) >> sh) & 0xFFFu], 1u);
            }
            __syncthreads();
            unsigned hh[8], part = 0;
            #pragma unroll
            for (int j = 0; j < 8; ++j) { hh[j] = sm.s.hist[8 * tid + j]; part += hh[j]; }
            unsigned sfx, total;
            block_suffix16(part, sm.s.wsum, wid, lane, sfx, total);
            const unsigned sfxn = sfx - part;
            if (sfx >= target && sfxn < target) {  // total >= target holds
                unsigned acc = sfxn;
                for (int k = 7; k >= 0; --k) {
                    if (acc + hh[k] >= target) {
                        sh_thresh = lo + ((unsigned)(8 * tid + k) << sh);
                        break;
                    }
                    acc += hh[k];
                }
            }
            __syncthreads();
            thresh = sh_thresh;
        }
    }

    // ---- Collect candidates >= thresh ----
    // key = (conf_bits<<32) | ~idx : larger == (higher conf, lower idx)
    // == lax.top_k order.
    for (int it = 0; it < mynit; it += 4) {
        unsigned long long cv[4];
        bool keep[4];
        #pragma unroll
        for (int k = 0; k < 4; ++k) {
            const int i = (it + k) * sstride + lbase;
            const bool v = (i < mycnt);
            cv[k] = v ? segp[i] : 0ull;
            keep[k] = v && ((unsigned)(cv[k] >> 32) >= thresh);
        }
        #pragma unroll
        for (int k = 0; k < 4; ++k)
            if (keep[k]) {
                const unsigned pos = atomicAdd(&sh_cnt, 1u);
                if (pos < (unsigned)CAP)
                    sm.s.buf[pos] = (cv[k] & 0xFFFFFFFF00000000ull) |
                                    (unsigned)(~(unsigned)cv[k]);
            }
    }
    __syncthreads();
    const int m = (int)min(sh_cnt, (unsigned)CAP);

    // ---- Rank-based emission (keys distinct -> ranks a permutation) ----
    float* const orow = out + (size_t)b * (2 * MAXDET * 5) +
                        (is_player ? 0 : MAXDET * 5);
    for (int i = tid; i < m; i += NT) {
        const unsigned long long k = sm.s.buf[i];
        int rank = 0;
        for (int j = 0; j < m; ++j) rank += (sm.s.buf[j] > k);
        if (rank < MAXDET) {
            const unsigned idx = ~(unsigned)k;
            const float conf = __uint_as_float((unsigned)(k >> 32));
            float o0, o1, o2, o3;
            if (is_player) {
                const int x = (int)idx % P_W;
                const int y = (int)idx / P_W;
                const float xc = (float)x * 16.0f + 7.5f;
                const float yc = (float)y * 16.0f + 7.5f;
                const float* bp = pbb + (size_t)b * 4 * P_HW + idx;
                const float t0 = bp[0 * P_HW] * 1920.0f;
                const float t1 = bp[1 * P_HW] * 1088.0f;
                const float t2 = bp[2 * P_HW] * 1920.0f;
                const float t3 = bp[3 * P_HW] * 1088.0f;
                const float bx = xc + t0, by = yc + t1;
                o0 = bx - 0.5f * t2;
                o1 = by - 0.5f * t3;
                o2 = bx + 0.5f * t2;
                o3 = by + 0.5f * t3;
            } else {
                const int x = (int)idx % B_W;
                const int y = (int)idx / B_W;
                const float xc = (float)x * 4.0f + 1.5f;
                const float yc = (float)y * 4.0f + 1.5f;
                o0 = xc - 10.0f;
                o1 = yc - 10.0f;
                o2 = xc + 10.0f;
                o3 = yc + 10.0f;
            }
            float* op = orow + rank * 5;
            op[0] = o0; op[1] = o1; op[2] = o2; op[3] = o3; op[4] = conf;
        }
    }
    if (m < MAXDET) {  // pathological; never hit with this data
        for (int r = m + tid; r < MAXDET; r += NT) {
            float* op = orow + r * 5;
            op[0] = op[1] = op[2] = op[3] = op[4] = 0.0f;
        }
    }
}

// ---------------------------------------------------------------------------

extern "C" void kernel_launch(void* const* d_in, const int* in_sizes, int n_in,
                              void* d_out, int out_size) {
    const float* pfm = nullptr;
    const float* pbb = nullptr;
    const float* bfm = nullptr;
    for (int i = 0; i < n_in; ++i) {
        if (in_sizes[i] == B_DIM * 2 * P_HW)      pfm = (const float*)d_in[i];
        else if (in_sizes[i] == B_DIM * 4 * P_HW) pbb = (const float*)d_in[i];
        else if (in_sizes[i] == B_DIM * 2 * B_HW) bfm = (const float*)d_in[i];
    }
    float* out = (float*)d_out;

    fused_kernel<<<GRID_CTAS, NT>>>(pfm, bfm, pbb, out);
}

// round 17
// speedup vs baseline: 1.1524x; 1.1087x over previous
#include <cuda_runtime.h>

// ---------------------------------------------------------------------------
// TemporalFootAndBall detection post-process, GB300 (sm_103a)  -- R17
//
// R17 = R13 (two-kernel champion; all fusion variants R14-R16 regressed and
// are abandoned) + ONE change: SoA candidate storage. Select's two scan
// passes only need the 4-byte conf key; idx is touched only for ~168 final
// keepers. Split key[]/idx[] arrays halve scan bytes and latency-chain
// length; batch widened 4->8.
// ---------------------------------------------------------------------------

#define B_DIM   64
#define P_H     68
#define P_W     120
#define P_HW    (P_H * P_W)
#define B_H     272
#define B_W     480
#define B_HW    (B_H * B_W)
#define MAXDET  100

#define NROWS      17                // rows per warp strip (ball & player)
#define CHUNKS_B   16                // ball row-chunks per batch (16*17=272)
#define CAP_B      (NROWS * B_W)     // 8160 (cap = pixels in chunk: safe)
#define BALL_CTAS  (B_DIM * CHUNKS_B)  // 1024
#define ALL_CTAS   (BALL_CTAS + B_DIM) // + 64 player CTAs

#define NWARP   16
#define WCAP    64                   // per-warp deferred-keeper buffer

// Static scratch (allocation-free). SoA: keys and indices separate.
__device__ unsigned g_key_b[(size_t)BALL_CTAS * CAP_B];
__device__ unsigned g_idx_b[(size_t)BALL_CTAS * CAP_B];
__device__ unsigned g_key_p[B_DIM * P_HW];
__device__ unsigned g_idx_p[B_DIM * P_HW];
__device__ int g_cnt_b[BALL_CTAS];   // plain stores, rewritten every launch
__device__ int g_cnt_p[B_DIM];

// Bit-exact replication of libdevice __nv_expf (XLA's f32 exp) for args in
// (-88, 0]. fma/exact-scale only -> fast-math-proof.
__device__ __forceinline__ float xla_expf(float a) {
    float j = fmaf(a, 0x1.715476p+0f, 0x1.8p+23f) - 0x1.8p+23f;  // rint
    float f = fmaf(j, -0x1.62e400p-1f, a);
    f = fmaf(j, -0x1.7f7d1cp-20f, f);
    const int i = (int)j;
    float r = 0x1.694000p-10f;
    r = fmaf(r, f, 0x1.125edcp-7f);
    r = fmaf(r, f, 0x1.555b5ap-5f);
    r = fmaf(r, f, 0x1.555450p-3f);
    r = fmaf(r, f, 0x1.fffff6p-2f);
    r = fmaf(r, f, 1.0f);
    r = fmaf(r, f, 1.0f);
    return r * __uint_as_float((unsigned)(127 + i) << 23);
}

// softmax([x0,x1])[1] as a function of d = x1-x0, bit-identical to
// m=max; e=exp(min-m); conf=e1/(1+e) with IEEE ops.
__device__ __forceinline__ float conf_from_d(float d) {
    const float e = xla_expf(0.0f - fabsf(d));
    const float e1 = (d >= 0.0f) ? 1.0f : e;
    return __fdiv_rn(e1, 1.0f + e);
}

// Range-adaptive monotone bin map for conf keys (conf in (0,1]):
//   key >= 0x3F000000 (conf >= 0.5): mantissa bins, 2^12 ulps wide
//   else: exponent bins (coarse; sparse population)
__device__ __forceinline__ unsigned key_bin(unsigned key) {
    return (key >= 0x3F000000u) ? (128u + ((key - 0x3F000000u) >> 12))
                                : (key >> 23);
}
__device__ __forceinline__ unsigned bin_lo(unsigned b) {
    return (b >= 128u) ? (0x3F000000u + ((b - 128u) << 12)) : (b << 23);
}
__device__ __forceinline__ int bin_shift(unsigned b) {
    return (b >= 128u) ? 0 : 11;   // sub-bin width shift for level-1
}

// Drain a warp's deferred-keeper buffer: compute exact conf keys in bulk
// (all lanes parallel) and write key/idx to the CTA's global segments.
__device__ __forceinline__ void warp_flush(unsigned long long* wb, int cnt,
                                           unsigned* segk, unsigned* segi,
                                           int* s_cnt, int lane) {
    if (cnt == 0) return;
    int base = 0;
    if (lane == 0) base = atomicAdd(s_cnt, cnt);
    base = __shfl_sync(0xFFFFFFFFu, base, 0);
    for (int i = lane; i < cnt; i += 32) {   // no collectives inside
        const unsigned long long e = wb[i];
        const float d = __uint_as_float((unsigned)(e >> 32));
        segk[base + i] = __float_as_uint(conf_from_d(d));
        segi[base + i] = (unsigned)e;
    }
}

// ---------------------------------------------------------------------------
// NMS strip worker: one warp owns a 30-output-column x NROWS strip. All
// NROWS+2 halo rows of d = x1-x0 are loaded into registers up-front (single
// latency wait), then the 3x3 NMS runs register-resident.
// ---------------------------------------------------------------------------
template <int H, int W>
__device__ __forceinline__ void nms_strip(const float* __restrict__ f0,
                                          int gx, int y0,
                                          unsigned long long* wb,
                                          unsigned* segk, unsigned* segi,
                                          int* s_cnt, int lane) {
    const float* f1 = f0 + H * W;
    const bool inx = (gx >= 0 && gx < W);
    const bool owner = inx && lane >= 1 && lane <= 30;
    const float NINF = __int_as_float(0xFF800000);

    // Batch-load all halo rows (independent loads -> full MLP).
    float d[NROWS + 2];
    #pragma unroll
    for (int i = 0; i < NROWS + 2; ++i) {
        const int y = y0 - 1 + i;
        d[i] = NINF;
        if (inx && y >= 0 && y < H) {
            const int o = y * W + gx;
            d[i] = f1[o] - f0[o];
        }
    }

    int wcnt = 0;
    int rowbase = y0 * W;
    #pragma unroll
    for (int r = 0; r < NROWS; ++r) {
        const float vm = fmaxf(fmaxf(d[r], d[r + 1]), d[r + 2]);
        const float vl = __shfl_up_sync(0xFFFFFFFFu, vm, 1);
        const float vr = __shfl_down_sync(0xFFFFFFFFu, vm, 1);
        const float p  = fmaxf(vm, fmaxf(vl, vr));  // pooled 3x3 max (incl c)

        const float c = d[r + 1];
        bool kept = owner && (c == p);
        // Near-tie guard (per-lane, no ballot): conf bits can collapse only
        // if (p-c) <= 2^-18 * e^{dm}; exponent test, 1-bit slack each way.
        if (owner && !kept) {
            const float dd = p - c;
            const float dmx = fmaxf(fabsf(c), fabsf(p));
            const int E = (int)((__float_as_uint(dd) >> 23) & 255u) - 127;
            if ((float)E < fmaf(dmx, 1.442695041f, -15.0f)) {
                if (__float_as_uint(conf_from_d(c)) ==
                    __float_as_uint(conf_from_d(p)))
                    kept = true;
            }
        }

        const unsigned bal = __ballot_sync(0xFFFFFFFFu, kept);
        if (wcnt + 32 > WCAP) {                  // warp-uniform flush check
            warp_flush(wb, wcnt, segk, segi, s_cnt, lane);
            wcnt = 0;
        }
        if (kept)
            wb[wcnt + __popc(bal & ((1u << lane) - 1u))] =
                ((unsigned long long)__float_as_uint(c) << 32) |
                (unsigned)(rowbase + gx);
        wcnt += __popc(bal);
        rowbase += W;
    }
    warp_flush(wb, wcnt, segk, segi, s_cnt, lane);
}

// grid.x in [0, 1024): ball chunk CTAs; [1024, 1088): player CTAs.
// Block = 512 threads = 16 warps.
__global__ __launch_bounds__(512) void nms_kernel(
    const float* __restrict__ pfm, const float* __restrict__ bfm) {
    __shared__ unsigned long long wbuf[NWARP][WCAP];
    __shared__ int s_cnt;
    const int tid = threadIdx.x, wid = tid >> 5, lane = tid & 31;
    if (tid == 0) s_cnt = 0;
    __syncthreads();

    if (blockIdx.x < BALL_CTAS) {
        const int b = blockIdx.x >> 4, chunk = blockIdx.x & 15;
        nms_strip<B_H, B_W>(bfm + (size_t)b * 2 * B_HW,
                            wid * 30 + lane - 1, chunk * NROWS,
                            wbuf[wid],
                            g_key_b + (size_t)blockIdx.x * CAP_B,
                            g_idx_b + (size_t)blockIdx.x * CAP_B,
                            &s_cnt, lane);
    } else {
        const int b = blockIdx.x - BALL_CTAS;
        const int wcol = wid & 3, rc = wid >> 2;  // 4 cols x 4 row-chunks
        nms_strip<P_H, P_W>(pfm + (size_t)b * 2 * P_HW,
                            wcol * 30 + lane - 1, rc * NROWS,
                            wbuf[wid],
                            g_key_p + (size_t)b * P_HW,
                            g_idx_p + (size_t)b * P_HW,
                            &s_cnt, lane);
    }
    __syncthreads();
    if (tid == 0) {
        if (blockIdx.x < BALL_CTAS) g_cnt_b[blockIdx.x] = s_cnt;
        else                        g_cnt_p[blockIdx.x - BALL_CTAS] = s_cnt;
    }
}

// ---------------------------------------------------------------------------
// Block suffix scan over 1024 partials using shuffles (2 barriers).
// ---------------------------------------------------------------------------
__device__ __forceinline__ void block_suffix(unsigned part, unsigned* wsum,
                                             int wid, int lane,
                                             unsigned& sfx, unsigned& total) {
    unsigned s = part;
    #pragma unroll
    for (int d = 1; d < 32; d <<= 1) {
        const unsigned v = __shfl_down_sync(0xFFFFFFFFu, s, d);
        if (lane + d < 32) s += v;
    }
    if (lane == 0) wsum[wid] = s;
    __syncthreads();
    unsigned t = wsum[lane];           // 32 warp totals (lane-indexed)
    #pragma unroll
    for (int d = 1; d < 32; d <<= 1) {
        const unsigned v = __shfl_down_sync(0xFFFFFFFFu, t, d);
        if (lane + d < 32) t += v;
    }
    total = __shfl_sync(0xFFFFFFFFu, t, 0);
    unsigned carry = __shfl_sync(0xFFFFFFFFu, t, (wid + 1) & 31);
    if (wid == 31) carry = 0;
    sfx = s + carry;
    __syncthreads();                   // wsum reusable afterwards
}

// ---------------------------------------------------------------------------
// Per-row top-100. One CTA per output row (128 CTAs, 1024 threads).
// Warps spread across 16 segments (2 warps each); scan loops collective-free
// with batch-8 4-byte key loads. Range-adaptive binning; collect loads idx
// only for keepers; rank-based emission.
// ---------------------------------------------------------------------------
__global__ __launch_bounds__(1024) void select_kernel(
    const float* __restrict__ pbb, float* __restrict__ out) {
    constexpr int CAP = 1024;
    constexpr int NT = 1024;
    __shared__ unsigned hist[4096];
    __shared__ unsigned wsum[32];
    __shared__ unsigned long long buf[CAP];
    __shared__ int s_cnts[CHUNKS_B];
    __shared__ unsigned sh_b0, sh_above0, sh_set0, sh_thresh, sh_cnt, sh_done;

    const int blk = blockIdx.x;
    const bool is_player = (blk < B_DIM);
    const int b = is_player ? blk : blk - B_DIM;
    const int tid = threadIdx.x, wid = tid >> 5, lane = tid & 31;
    const int nseg = is_player ? 1 : CHUNKS_B;
    const int myseg = wid & (nseg - 1);        // warp's segment
    const int sub = wid / nseg;                // warp index within segment
    const int sstride = (32 / nseg) * 32;      // lanes per segment per iter

    if (tid < nseg)
        s_cnts[tid] = is_player ? g_cnt_p[b] : g_cnt_b[b * CHUNKS_B + tid];
    if (tid == 0) { sh_cnt = 0; sh_done = 0; sh_thresh = 0; }
    for (int i = tid; i < 4096; i += NT) hist[i] = 0;
    __syncthreads();

    const unsigned* const segk =
        is_player ? (g_key_p + (size_t)b * P_HW)
                  : (g_key_b + (size_t)(b * CHUNKS_B + myseg) * CAP_B);
    const unsigned* const segi =
        is_player ? (g_idx_p + (size_t)b * P_HW)
                  : (g_idx_b + (size_t)(b * CHUNKS_B + myseg) * CAP_B);
    const int mycnt = s_cnts[myseg];           // warp-uniform
    const int mynit = (mycnt + sstride - 1) / sstride;
    const int lbase = sub * 32 + lane;

    // ---- Level 0 histogram (range-adaptive bins; batch-8 key loads) ----
    for (int it = 0; it < mynit; it += 8) {
        unsigned bins[8];
        bool on[8];
        #pragma unroll
        for (int k = 0; k < 8; ++k) {
            const int i = (it + k) * sstride + lbase;
            on[k] = (i < mycnt);
            bins[k] = on[k] ? key_bin(segk[i]) : 0u;
        }
        #pragma unroll
        for (int k = 0; k < 8; ++k)
            if (on[k]) atomicAdd(&hist[bins[k]], 1u);
    }
    __syncthreads();

    {
        const unsigned h0 = hist[4 * tid],     h1 = hist[4 * tid + 1];
        const unsigned h2 = hist[4 * tid + 2], h3 = hist[4 * tid + 3];
        const unsigned part = h0 + h1 + h2 + h3;
        unsigned sfx, total;
        block_suffix(part, wsum, wid, lane, sfx, total);
        const unsigned sfxn = sfx - part;
        if (total < (unsigned)MAXDET) {
            if (tid == 0) sh_done = 1;         // collect-all path
        } else if (sfx >= (unsigned)MAXDET && sfxn < (unsigned)MAXDET) {
            unsigned acc = sfxn;
            const unsigned hh[4] = {h0, h1, h2, h3};
            for (int k = 3; k >= 0; --k) {
                if (acc + hh[k] >= (unsigned)MAXDET) {
                    sh_b0 = (unsigned)(4 * tid + k);
                    sh_above0 = acc;
                    sh_set0 = acc + hh[k];
                    break;
                }
                acc += hh[k];
            }
        }
    }
    __syncthreads();

    unsigned thresh = 0;
    if (!sh_done) {
        if (sh_set0 <= 168u) {                 // common: fine bins -> small set
            thresh = bin_lo(sh_b0);
        } else {
            // ---- Level 1 within boundary bin (generic sub-bins) ----
            const unsigned b0 = sh_b0;
            const unsigned lo = bin_lo(b0);
            const int sh = bin_shift(b0);      // 0 (exact) or 11
            const unsigned target = (unsigned)MAXDET - sh_above0;
            for (int i = tid; i < 4096; i += NT) hist[i] = 0;
            __syncthreads();
            for (int it = 0; it < mynit; it += 8) {
                unsigned sc[8];
                bool on[8];
                #pragma unroll
                for (int k = 0; k < 8; ++k) {
                    const int i = (it + k) * sstride + lbase;
                    const bool v = (i < mycnt);
                    sc[k] = v ? segk[i] : 0u;
                    on[k] = v && (key_bin(sc[k]) == b0);
                }
                #pragma unroll
                for (int k = 0; k < 8; ++k)
                    if (on[k])
                        atomicAdd(&hist[((sc[k] - lo) >> sh) & 0xFFFu], 1u);
            }
            __syncthreads();
            const unsigned g0 = hist[4 * tid],     g1 = hist[4 * tid + 1];
            const unsigned g2 = hist[4 * tid + 2], g3 = hist[4 * tid + 3];
            const unsigned part = g0 + g1 + g2 + g3;
            unsigned sfx, total;
            block_suffix(part, wsum, wid, lane, sfx, total);
            const unsigned sfxn = sfx - part;
            if (sfx >= target && sfxn < target) {  // total >= target holds
                unsigned acc = sfxn;
                const unsigned hh[4] = {g0, g1, g2, g3};
                for (int k = 3; k >= 0; --k) {
                    if (acc + hh[k] >= target) {
                        sh_thresh = lo + ((unsigned)(4 * tid + k) << sh);
                        break;
                    }
                    acc += hh[k];
                }
            }
            __syncthreads();
            thresh = sh_thresh;
        }
    }

    // ---- Collect candidates >= thresh (keys batch-8; idx only if kept) ----
    // key64 = (key<<32) | ~idx : larger == (higher conf, lower idx)
    // == lax.top_k order.
    for (int it = 0; it < mynit; it += 8) {
        unsigned kv[8];
        bool keep[8];
        #pragma unroll
        for (int k = 0; k < 8; ++k) {
            const int i = (it + k) * sstride + lbase;
            const bool v = (i < mycnt);
            kv[k] = v ? segk[i] : 0u;
            keep[k] = v && (kv[k] >= thresh) && (thresh != 0u || v);
        }
        #pragma unroll
        for (int k = 0; k < 8; ++k)
            if (keep[k]) {
                const int i = (it + k) * sstride + lbase;
                const unsigned pos = atomicAdd(&sh_cnt, 1u);
                if (pos < (unsigned)CAP)
                    buf[pos] = ((unsigned long long)kv[k] << 32) |
                               (unsigned)(~segi[i]);
            }
    }
    __syncthreads();
    const int m = (int)min(sh_cnt, (unsigned)CAP);

    // ---- Rank-based emission (keys distinct -> ranks a permutation) ----
    float* const orow = out + (size_t)b * (2 * MAXDET * 5) +
                        (is_player ? 0 : MAXDET * 5);
    for (int i = tid; i < m; i += NT) {
        const unsigned long long k = buf[i];
        int rank = 0;
        for (int j = 0; j < m; ++j) rank += (buf[j] > k);
        if (rank < MAXDET) {
            const unsigned idx = ~(unsigned)k;
            const float conf = __uint_as_float((unsigned)(k >> 32));
            float o0, o1, o2, o3;
            if (is_player) {
                const int x = (int)idx % P_W;
                const int y = (int)idx / P_W;
                const float xc = (float)x * 16.0f + 7.5f;
                const float yc = (float)y * 16.0f + 7.5f;
                const float* bp = pbb + (size_t)b * 4 * P_HW + idx;
                const float t0 = bp[0 * P_HW] * 1920.0f;
                const float t1 = bp[1 * P_HW] * 1088.0f;
                const float t2 = bp[2 * P_HW] * 1920.0f;
                const float t3 = bp[3 * P_HW] * 1088.0f;
                const float bx = xc + t0, by = yc + t1;
                o0 = bx - 0.5f * t2;
                o1 = by - 0.5f * t3;
                o2 = bx + 0.5f * t2;
                o3 = by + 0.5f * t3;
            } else {
                const int x = (int)idx % B_W;
                const int y = (int)idx / B_W;
                const float xc = (float)x * 4.0f + 1.5f;
                const float yc = (float)y * 4.0f + 1.5f;
                o0 = xc - 10.0f;
                o1 = yc - 10.0f;
                o2 = xc + 10.0f;
                o3 = yc + 10.0f;
            }
            float* op = orow + rank * 5;
            op[0] = o0; op[1] = o1; op[2] = o2; op[3] = o3; op[4] = conf;
        }
    }
    if (m < MAXDET) {  // pathological; never hit with this data
        for (int r = m + tid; r < MAXDET; r += NT) {
            float* op = orow + r * 5;
            op[0] = op[1] = op[2] = op[3] = op[4] = 0.0f;
        }
    }
}

// ---------------------------------------------------------------------------

extern "C" void kernel_launch(void* const* d_in, const int* in_sizes, int n_in,
                              void* d_out, int out_size) {
    const float* pfm = nullptr;
    const float* pbb = nullptr;
    const float* bfm = nullptr;
    for (int i = 0; i < n_in; ++i) {
        if (in_sizes[i] == B_DIM * 2 * P_HW)      pfm = (const float*)d_in[i];
        else if (in_sizes[i] == B_DIM * 4 * P_HW) pbb = (const float*)d_in[i];
        else if (in_sizes[i] == B_DIM * 2 * B_HW) bfm = (const float*)d_in[i];
    }
    float* out = (float*)d_out;

    nms_kernel<<<ALL_CTAS, 512>>>(pfm, bfm);
    select_kernel<<<2 * B_DIM, 1024>>>(pbb, out);
}